// round 1
// baseline (speedup 1.0000x reference)
#include <cuda_runtime.h>
#include <cstdint>

// Problem constants
#define HID   1024
#define INP   128
#define NBAT  32
#define LSTEP 2048
#define KTOT  1152            // 1024 (h) + 128 (x)
#define SPAD  1156            // padded row stride in floats (mod 32 == 4 -> conflict-free)
#define COLS  32              // hidden columns per CTA
#define ROWSB 8               // batch rows per CTA
#define NCOLB 32              // column blocks
#define NBATB 4               // batch blocks
#define GRID  (NCOLB * NBATB) // 128 CTAs (<= 148 SMs, single wave)
#define NTHR  256
#define KW    144             // K slice per warp (8 warps)
#define NITER (KW / 4)        // 36 iterations of 4-k chunks

// Global barrier state (zero-initialized at module load; self-cleaning across launches)
__device__ unsigned g_cnt = 0;
__device__ volatile unsigned g_flag = 0;

// Packed dual fp32 FMA (sm_100+): d.lo = a.lo*b.lo + c.lo ; d.hi likewise
__device__ __forceinline__ unsigned long long fma2(unsigned long long a,
                                                   unsigned long long b,
                                                   unsigned long long c) {
    unsigned long long d;
    asm("fma.rn.f32x2 %0, %1, %2, %3;" : "=l"(d) : "l"(a), "l"(b), "l"(c));
    return d;
}

__device__ __forceinline__ float unpack_sum(unsigned long long v) {
    float lo, hi;
    asm("mov.b64 {%0, %1}, %2;" : "=f"(lo), "=f"(hi) : "l"(v));
    return lo + hi;
}

// smem layout (floats):
//   W_s   [COLS][SPAD]   : 32*1156 = 36992   (concat [W_h row | W_in row])
//   HX_s  [ROWSB][SPAD]  :  8*1156 =  9248   (concat [h(t-1) | x_t])
//   part  [8][ROWSB][COLS]:           2048
//   bias_s[COLS]         :              32
#define SM_W   0
#define SM_HX  (COLS * SPAD)
#define SM_P   (SM_HX + ROWSB * SPAD)
#define SM_B   (SM_P + 8 * ROWSB * COLS)
#define SM_TOT (SM_B + COLS)                 // 48320 floats = 193280 bytes

__global__ void __launch_bounds__(NTHR, 1)
reservoir_persistent(const float* __restrict__ input,   // (L, N, I)
                     const float* __restrict__ h_init,  // (N, H)
                     const float* __restrict__ W_in,    // (H, I)
                     const float* __restrict__ bias,    // (H)
                     const float* __restrict__ W_h,     // (H, H)
                     float* __restrict__ out)           // (L, N, H)
{
    extern __shared__ float smem[];
    float* W_s    = smem + SM_W;
    float* HX_s   = smem + SM_HX;
    float* part_s = smem + SM_P;
    float* bias_s = smem + SM_B;

    const int tid  = threadIdx.x;
    const int bx   = blockIdx.x;
    const int j0   = (bx & (NCOLB - 1)) * COLS;  // column block origin
    const int n0   = (bx >> 5) * ROWSB;          // batch block origin

    // Epoch base for the global barrier (monotonic across graph replays)
    unsigned bar_base = 0;
    if (tid == 0) bar_base = g_flag;

    // ---- One-time: load W slice ([W_h | W_in] for our 32 columns) + bias ----
    for (int i = tid; i < COLS * KTOT; i += NTHR) {
        int j = i / KTOT;
        int k = i - j * KTOT;
        float v = (k < HID) ? W_h[(size_t)(j0 + j) * HID + k]
                            : W_in[(size_t)(j0 + j) * INP + (k - HID)];
        W_s[j * SPAD + k] = v;
    }
    if (tid < COLS) bias_s[tid] = bias[j0 + tid];
    __syncthreads();

    // Warp/lane geometry for compute
    const int w    = tid >> 5;
    const int lane = tid & 31;
    const int k0   = w * KW;
    const int nb   = 2 * (lane >> 3);   // batch sub-row base {0,2,4,6}
    const int jb   = lane & 7;          // column sub-base; lane owns j = jb + 8*jj

    const ulonglong2* hx0p = (const ulonglong2*)(HX_s + nb * SPAD + k0);
    const ulonglong2* hx1p = (const ulonglong2*)(HX_s + (nb + 1) * SPAD + k0);
    const ulonglong2* w0p  = (const ulonglong2*)(W_s + (jb +  0) * SPAD + k0);
    const ulonglong2* w1p  = (const ulonglong2*)(W_s + (jb +  8) * SPAD + k0);
    const ulonglong2* w2p  = (const ulonglong2*)(W_s + (jb + 16) * SPAD + k0);
    const ulonglong2* w3p  = (const ulonglong2*)(W_s + (jb + 24) * SPAD + k0);

    // Reduction read indices
    const int rn = tid >> 5;       // 0..7 batch row
    const int rj = tid & 31;       // 0..31 column

    for (int t = 0; t < LSTEP; ++t) {
        // ---- Stage h(t-1) and x_t into smem ----
        const float* hsrc = (t == 0) ? (h_init + (size_t)n0 * HID)
                                     : (out + ((size_t)(t - 1) * NBAT + n0) * HID);
        // h part: 8 rows x 256 float4
        #pragma unroll
        for (int i = tid; i < ROWSB * (HID / 4); i += NTHR) {
            int n = i >> 8;           // /256
            int q = i & 255;
            float4 v = ((const float4*)(hsrc + (size_t)n * HID))[q];
            *(float4*)(HX_s + n * SPAD + 4 * q) = v;
        }
        // x part: 8 rows x 32 float4 (exactly 256 threads)
        {
            int n = tid >> 5;
            int q = tid & 31;
            float4 v = ((const float4*)(input + ((size_t)t * NBAT + n0 + n) * INP))[q];
            *(float4*)(HX_s + n * SPAD + HID + 4 * q) = v;
        }
        __syncthreads();

        // ---- Partial dot products over this warp's K-slice ----
        unsigned long long acc[8];
        #pragma unroll
        for (int i = 0; i < 8; ++i) acc[i] = 0ull;

        #pragma unroll 4
        for (int it = 0; it < NITER; ++it) {
            ulonglong2 a0 = hx0p[it];
            ulonglong2 a1 = hx1p[it];
            ulonglong2 b0 = w0p[it];
            ulonglong2 b1 = w1p[it];
            ulonglong2 b2 = w2p[it];
            ulonglong2 b3 = w3p[it];
            acc[0] = fma2(a0.x, b0.x, acc[0]); acc[0] = fma2(a0.y, b0.y, acc[0]);
            acc[1] = fma2(a0.x, b1.x, acc[1]); acc[1] = fma2(a0.y, b1.y, acc[1]);
            acc[2] = fma2(a0.x, b2.x, acc[2]); acc[2] = fma2(a0.y, b2.y, acc[2]);
            acc[3] = fma2(a0.x, b3.x, acc[3]); acc[3] = fma2(a0.y, b3.y, acc[3]);
            acc[4] = fma2(a1.x, b0.x, acc[4]); acc[4] = fma2(a1.y, b0.y, acc[4]);
            acc[5] = fma2(a1.x, b1.x, acc[5]); acc[5] = fma2(a1.y, b1.y, acc[5]);
            acc[6] = fma2(a1.x, b2.x, acc[6]); acc[6] = fma2(a1.y, b2.y, acc[6]);
            acc[7] = fma2(a1.x, b3.x, acc[7]); acc[7] = fma2(a1.y, b3.y, acc[7]);
        }

        // ---- Dump partials to smem ----
        #pragma unroll
        for (int nn = 0; nn < 2; ++nn)
            #pragma unroll
            for (int jj = 0; jj < 4; ++jj)
                part_s[(w * ROWSB + (nb + nn)) * COLS + (jb + 8 * jj)]
                    = unpack_sum(acc[nn * 4 + jj]);
        __syncthreads();

        // ---- Cross-warp reduce + bias + tanh + store h(t) ----
        {
            float s = bias_s[rj];
            #pragma unroll
            for (int ww = 0; ww < 8; ++ww)
                s += part_s[(ww * ROWSB + rn) * COLS + rj];
            float hv = tanhf(s);
            out[((size_t)t * NBAT + n0 + rn) * HID + j0 + rj] = hv;
        }
        __syncthreads();

        // ---- Grid-wide barrier (epoch-based, self-cleaning) ----
        if (tid == 0) {
            __threadfence();
            unsigned target = bar_base + (unsigned)t + 1u;
            if (atomicAdd(&g_cnt, 1u) == (unsigned)(gridDim.x - 1)) {
                g_cnt = 0u;
                __threadfence();
                g_flag = target;
            } else {
                while (g_flag < target) { }
                __threadfence();
            }
        }
        __syncthreads();
    }
}

extern "C" void kernel_launch(void* const* d_in, const int* in_sizes, int n_in,
                              void* d_out, int out_size) {
    (void)in_sizes; (void)n_in; (void)out_size;
    const float* input  = (const float*)d_in[0];  // (2048, 32, 128)
    const float* h_init = (const float*)d_in[1];  // (32, 1024)
    const float* W_in   = (const float*)d_in[2];  // (1024, 128)
    const float* bias   = (const float*)d_in[3];  // (1024)
    const float* W_h    = (const float*)d_in[4];  // (1024, 1024)
    float* out = (float*)d_out;                   // (2048, 32, 1024)

    cudaFuncSetAttribute(reservoir_persistent,
                         cudaFuncAttributeMaxDynamicSharedMemorySize,
                         SM_TOT * (int)sizeof(float));
    reservoir_persistent<<<GRID, NTHR, SM_TOT * sizeof(float)>>>(
        input, h_init, W_in, bias, W_h, out);
}

// round 4
// speedup vs baseline: 1.0150x; 1.0150x over previous
#include <cuda_runtime.h>
#include <cstdint>

// Problem constants
#define HID   1024
#define INP   128
#define NBAT  32
#define LSTEP 2048
#define KTOT  1152            // 1024 (h) + 128 (x)
#define SPAD  1156            // padded row stride in floats
#define COLS  32              // hidden columns per CTA
#define ROWSB 8               // batch rows per CTA
#define NCOLB 32              // column blocks
#define NBATB 4               // batch groups
#define GRID  (NCOLB * NBATB) // 128 CTAs (single wave)
#define NTHR  512
#define NWARP 16
#define KW    (KTOT / NWARP)  // 72 floats per warp K-slice
#define NITER (KW / 4)        // 18 iterations of 4-k chunks

// Per-GROUP barrier state: R1's proven protocol, partitioned 4 ways.
// Zero-initialized at module load; self-cleaning (epoch-monotonic) across
// launches/replays.
__device__ unsigned g_cnt[NBATB];
__device__ volatile unsigned g_flag[NBATB];

// Packed dual fp32 FMA (sm_100+)
__device__ __forceinline__ unsigned long long fma2(unsigned long long a,
                                                   unsigned long long b,
                                                   unsigned long long c) {
    unsigned long long d;
    asm("fma.rn.f32x2 %0, %1, %2, %3;" : "=l"(d) : "l"(a), "l"(b), "l"(c));
    return d;
}

__device__ __forceinline__ float unpack_sum(unsigned long long v) {
    float lo, hi;
    asm("mov.b64 {%0, %1}, %2;" : "=f"(lo), "=f"(hi) : "l"(v));
    return lo + hi;
}

// smem layout (floats):
//   W_s   [COLS][SPAD]        : 32*1156 = 36992
//   HX_s  [ROWSB][SPAD]       :  8*1156 =  9248
//   part  [NWARP][ROWSB][COLS]:           4096
//   bias_s[COLS]              :             32
#define SM_W   0
#define SM_HX  (COLS * SPAD)
#define SM_P   (SM_HX + ROWSB * SPAD)
#define SM_B   (SM_P + NWARP * ROWSB * COLS)
#define SM_TOT (SM_B + COLS)                 // 50368 floats = 201472 bytes

__global__ void __launch_bounds__(NTHR, 1)
reservoir_persistent(const float* __restrict__ input,   // (L, N, I)
                     const float* __restrict__ h_init,  // (N, H)
                     const float* __restrict__ W_in,    // (H, I)
                     const float* __restrict__ bias,    // (H)
                     const float* __restrict__ W_h,     // (H, H)
                     float* __restrict__ out)           // (L, N, H)
{
    extern __shared__ float smem[];
    float* W_s    = smem + SM_W;
    float* HX_s   = smem + SM_HX;
    float* part_s = smem + SM_P;
    float* bias_s = smem + SM_B;

    const int tid = threadIdx.x;
    const int bx  = blockIdx.x;
    const int c   = bx & (NCOLB - 1);   // column block id
    const int g   = bx >> 5;            // batch group id
    const int j0  = c * COLS;
    const int n0  = g * ROWSB;

    // Epoch base for this group's barrier (tid0 only, exactly as in R1)
    unsigned bar_base = 0;
    if (tid == 0) bar_base = g_flag[g];

    // ---- One-time: load W slice ([W_h | W_in] for our 32 columns) + bias ----
    for (int i = tid; i < COLS * KTOT; i += NTHR) {
        int j = i / KTOT;
        int k = i - j * KTOT;
        float v = (k < HID) ? W_h[(size_t)(j0 + j) * HID + k]
                            : W_in[(size_t)(j0 + j) * INP + (k - HID)];
        W_s[j * SPAD + k] = v;
    }
    if (tid < COLS) bias_s[tid] = bias[j0 + tid];
    __syncthreads();

    // Warp/lane geometry for compute
    const int w    = tid >> 5;
    const int lane = tid & 31;
    const int k0   = w * KW;
    const int nb   = 2 * (lane >> 3);   // batch sub-row base {0,2,4,6}
    const int jb   = lane & 7;          // column sub-base

    const ulonglong2* hx0p = (const ulonglong2*)(HX_s + nb * SPAD + k0);
    const ulonglong2* hx1p = (const ulonglong2*)(HX_s + (nb + 1) * SPAD + k0);
    const ulonglong2* w0p  = (const ulonglong2*)(W_s + (jb +  0) * SPAD + k0);
    const ulonglong2* w1p  = (const ulonglong2*)(W_s + (jb +  8) * SPAD + k0);
    const ulonglong2* w2p  = (const ulonglong2*)(W_s + (jb + 16) * SPAD + k0);
    const ulonglong2* w3p  = (const ulonglong2*)(W_s + (jb + 24) * SPAD + k0);

    // Reduction indices (first 256 threads)
    const int rn = tid >> 5;
    const int rj = tid & 31;

    for (int t = 0; t < LSTEP; ++t) {
        // ---- Stage h(t-1): 8 rows x 1024 floats = 2048 float4 ----
        const float* hsrc = (t == 0) ? (h_init + (size_t)n0 * HID)
                                     : (out + ((size_t)(t - 1) * NBAT + n0) * HID);
        #pragma unroll
        for (int rep = 0; rep < 4; ++rep) {
            int i = tid + rep * NTHR;
            int n = i >> 8;
            int q = i & 255;
            float4 v = ((const float4*)(hsrc + (size_t)n * HID))[q];
            *(float4*)(HX_s + n * SPAD + 4 * q) = v;
        }
        // ---- Stage x_t: 8 rows x 32 float4 ----
        if (tid < 256) {
            int n = tid >> 5;
            int q = tid & 31;
            float4 v = ((const float4*)(input + ((size_t)t * NBAT + n0 + n) * INP))[q];
            *(float4*)(HX_s + n * SPAD + HID + 4 * q) = v;
        }
        __syncthreads();

        // ---- Partial dot products over this warp's K-slice ----
        unsigned long long acc[8];
        #pragma unroll
        for (int i = 0; i < 8; ++i) acc[i] = 0ull;

        #pragma unroll 3
        for (int it = 0; it < NITER; ++it) {
            ulonglong2 a0 = hx0p[it];
            ulonglong2 a1 = hx1p[it];
            ulonglong2 b0 = w0p[it];
            ulonglong2 b1 = w1p[it];
            ulonglong2 b2 = w2p[it];
            ulonglong2 b3 = w3p[it];
            acc[0] = fma2(a0.x, b0.x, acc[0]); acc[0] = fma2(a0.y, b0.y, acc[0]);
            acc[1] = fma2(a0.x, b1.x, acc[1]); acc[1] = fma2(a0.y, b1.y, acc[1]);
            acc[2] = fma2(a0.x, b2.x, acc[2]); acc[2] = fma2(a0.y, b2.y, acc[2]);
            acc[3] = fma2(a0.x, b3.x, acc[3]); acc[3] = fma2(a0.y, b3.y, acc[3]);
            acc[4] = fma2(a1.x, b0.x, acc[4]); acc[4] = fma2(a1.y, b0.y, acc[4]);
            acc[5] = fma2(a1.x, b1.x, acc[5]); acc[5] = fma2(a1.y, b1.y, acc[5]);
            acc[6] = fma2(a1.x, b2.x, acc[6]); acc[6] = fma2(a1.y, b2.y, acc[6]);
            acc[7] = fma2(a1.x, b3.x, acc[7]); acc[7] = fma2(a1.y, b3.y, acc[7]);
        }

        // ---- Dump partials ----
        #pragma unroll
        for (int nn = 0; nn < 2; ++nn)
            #pragma unroll
            for (int jj = 0; jj < 4; ++jj)
                part_s[(w * ROWSB + (nb + nn)) * COLS + (jb + 8 * jj)]
                    = unpack_sum(acc[nn * 4 + jj]);
        __syncthreads();

        // ---- Reduce 16 partials + bias + tanh + store h(t) ----
        if (tid < 256) {
            float s = bias_s[rj];
            #pragma unroll
            for (int ww = 0; ww < NWARP; ++ww)
                s += part_s[(ww * ROWSB + rn) * COLS + rj];
            float hv = tanhf(s);
            out[((size_t)t * NBAT + n0 + rn) * HID + j0 + rj] = hv;
        }
        __syncthreads();

        // ---- Group-wide barrier: R1's exact protocol, 32 CTAs per group ----
        if (tid == 0) {
            __threadfence();
            unsigned target = bar_base + (unsigned)t + 1u;
            if (atomicAdd(&g_cnt[g], 1u) == (unsigned)(NCOLB - 1)) {
                g_cnt[g] = 0u;
                __threadfence();
                g_flag[g] = target;
            } else {
                while (g_flag[g] < target) { }
                __threadfence();
            }
        }
        __syncthreads();
    }
}

extern "C" void kernel_launch(void* const* d_in, const int* in_sizes, int n_in,
                              void* d_out, int out_size) {
    (void)in_sizes; (void)n_in; (void)out_size;
    const float* input  = (const float*)d_in[0];  // (2048, 32, 128)
    const float* h_init = (const float*)d_in[1];  // (32, 1024)
    const float* W_in   = (const float*)d_in[2];  // (1024, 128)
    const float* bias   = (const float*)d_in[3];  // (1024)
    const float* W_h    = (const float*)d_in[4];  // (1024, 1024)
    float* out = (float*)d_out;                   // (2048, 32, 1024)

    cudaFuncSetAttribute(reservoir_persistent,
                         cudaFuncAttributeMaxDynamicSharedMemorySize,
                         SM_TOT * (int)sizeof(float));
    reservoir_persistent<<<GRID, NTHR, SM_TOT * sizeof(float)>>>(
        input, h_init, W_in, bias, W_h, out);
}

// round 5
// speedup vs baseline: 1.1898x; 1.1723x over previous
#include <cuda_runtime.h>
#include <cstdint>

// Problem constants
#define HID   1024
#define INP   128
#define NBAT  32
#define LSTEP 2048
#define KTOT  1152            // 1024 (h) + 128 (x)
#define COLS  32              // hidden columns per CTA
#define ROWSB 8               // batch rows per CTA
#define NCOLB 32              // column blocks
#define NBATB 4               // batch groups
#define GRID  (NCOLB * NBATB) // 128 CTAs (single wave)
#define NTHR  512
#define NWARP 16
#define KW    (KTOT / NWARP)  // 72 k per warp
#define NCH   (KW / 4)        // 18 chunks of 4 k
#define NWF   (KW / 2)        // 36 f32x2 W registers per lane

// Per-GROUP barrier state (R4's proven protocol).
__device__ unsigned g_cnt[NBATB];
__device__ volatile unsigned g_flag[NBATB];

// Packed dual fp32 FMA (sm_100+)
__device__ __forceinline__ unsigned long long fma2(unsigned long long a,
                                                   unsigned long long b,
                                                   unsigned long long c) {
    unsigned long long d;
    asm("fma.rn.f32x2 %0, %1, %2, %3;" : "=l"(d) : "l"(a), "l"(b), "l"(c));
    return d;
}

__device__ __forceinline__ unsigned long long pack2(float x, float y) {
    unsigned long long r;
    asm("mov.b64 %0, {%1, %2};" : "=l"(r) : "f"(x), "f"(y));
    return r;
}

__device__ __forceinline__ float unpack_sum(unsigned long long v) {
    float lo, hi;
    asm("mov.b64 {%0, %1}, %2;" : "=f"(lo), "=f"(hi) : "l"(v));
    return lo + hi;
}

// smem layout (floats):
//   HP    [ROWSB][KTOT]  : 8*1152 = 9216   ([h(t-1) | x_t] per row, contiguous)
//   part  [ROWSB][COLS][17]:        4352   (pad 17 -> conflict-free stride)
//   bias_s[COLS]         :            32
#define HROW   KTOT
#define SM_HP  0
#define SM_P   (ROWSB * HROW)
#define PSTR   17
#define SM_B   (SM_P + ROWSB * COLS * PSTR)
#define SM_TOT (SM_B + COLS)            // 13600 floats = 54400 bytes

__global__ void __launch_bounds__(NTHR, 1)
reservoir_persistent(const float* __restrict__ input,   // (L, N, I)
                     const float* __restrict__ h_init,  // (N, H)
                     const float* __restrict__ W_in,    // (H, I)
                     const float* __restrict__ bias,    // (H)
                     const float* __restrict__ W_h,     // (H, H)
                     float* __restrict__ out)           // (L, N, H)
{
    extern __shared__ float smem[];
    float* HP     = smem + SM_HP;
    float* part_s = smem + SM_P;
    float* bias_s = smem + SM_B;

    const int tid = threadIdx.x;
    const int bx  = blockIdx.x;
    const int c   = bx & (NCOLB - 1);   // column block id
    const int g   = bx >> 5;            // batch group id
    const int j0  = c * COLS;
    const int n0  = g * ROWSB;

    // Epoch base for this group's barrier (tid0 only)
    unsigned bar_base = 0;
    if (tid == 0) bar_base = g_flag[g];

    const int w    = tid >> 5;          // warp id = K-slice
    const int lane = tid & 31;          // lane id = column within block
    const int k0   = w * KW;
    const int col  = j0 + lane;

    // ---- One-time: W slice into REGISTERS (f32x2-packed along k) ----
    // k0 and the h/x boundary (1024) are both even -> no pair straddles.
    unsigned long long wreg[NWF];
    #pragma unroll
    for (int i = 0; i < NWF; ++i) {
        int k = k0 + 2 * i;
        float2 v;
        if (k < HID) v = *(const float2*)(W_h + (size_t)col * HID + k);
        else         v = *(const float2*)(W_in + (size_t)col * INP + (k - HID));
        wreg[i] = pack2(v.x, v.y);
    }
    if (tid < COLS) bias_s[tid] = bias[j0 + tid];

    // Reduction indices (first 256 threads)
    const int rn = tid >> 5;
    const int rj = tid & 31;

    const char* abase = (const char*)HP + (size_t)k0 * 4;  // this warp's k origin

    for (int t = 0; t < LSTEP; ++t) {
        // ---- Stage h(t-1): 8 rows x 1024 floats, contiguous per row ----
        const float* hsrc = (t == 0) ? (h_init + (size_t)n0 * HID)
                                     : (out + ((size_t)(t - 1) * NBAT + n0) * HID);
        #pragma unroll
        for (int rep = 0; rep < 4; ++rep) {
            int i = tid + rep * NTHR;   // 0..2047
            int n = i >> 8;
            int q = i & 255;
            float4 v = ((const float4*)(hsrc + (size_t)n * HID))[q];
            *(float4*)(HP + n * HROW + 4 * q) = v;
        }
        // ---- Stage x_t: 8 rows x 32 float4 ----
        if (tid < 256) {
            int n = tid >> 5;
            int q = tid & 31;
            float4 v = ((const float4*)(input + ((size_t)t * NBAT + n0 + n) * INP))[q];
            *(float4*)(HP + n * HROW + HID + 4 * q) = v;
        }
        __syncthreads();

        // ---- Compute: lane=col, broadcast h reads, W from registers ----
        unsigned long long acc[ROWSB];
        #pragma unroll
        for (int i = 0; i < ROWSB; ++i) acc[i] = 0ull;

        #pragma unroll
        for (int ch = 0; ch < NCH; ++ch) {
            // Each chunk covers k offsets [4ch, 4ch+4) = f32x2 pair (2ch, 2ch+1)
            #pragma unroll
            for (int np = 0; np < 4; ++np) {
                // 16B broadcast per row: (kp, kp+1) packed pairs
                ulonglong2 a0 = *(const ulonglong2*)(abase + (2 * np)     * (HROW * 4) + 16 * ch);
                ulonglong2 a1 = *(const ulonglong2*)(abase + (2 * np + 1) * (HROW * 4) + 16 * ch);
                acc[2 * np]     = fma2(a0.x, wreg[2 * ch],     acc[2 * np]);
                acc[2 * np]     = fma2(a0.y, wreg[2 * ch + 1], acc[2 * np]);
                acc[2 * np + 1] = fma2(a1.x, wreg[2 * ch],     acc[2 * np + 1]);
                acc[2 * np + 1] = fma2(a1.y, wreg[2 * ch + 1], acc[2 * np + 1]);
            }
        }

        // ---- Dump partials: part[n][lane][w], stride-17 conflict-free ----
        #pragma unroll
        for (int n = 0; n < ROWSB; ++n)
            part_s[(n * COLS + lane) * PSTR + w] = unpack_sum(acc[n]);
        __syncthreads();

        // ---- Reduce 16 partials + bias + tanh + store h(t) ----
        if (tid < 256) {
            float s = bias_s[rj];
            #pragma unroll
            for (int ww = 0; ww < NWARP; ++ww)
                s += part_s[(rn * COLS + rj) * PSTR + ww];
            float hv = tanhf(s);
            out[((size_t)t * NBAT + n0 + rn) * HID + j0 + rj] = hv;
        }
        __syncthreads();

        // ---- Group-wide barrier (R4's proven protocol, 32 CTAs/group) ----
        if (tid == 0) {
            __threadfence();
            unsigned target = bar_base + (unsigned)t + 1u;
            if (atomicAdd(&g_cnt[g], 1u) == (unsigned)(NCOLB - 1)) {
                g_cnt[g] = 0u;
                __threadfence();
                g_flag[g] = target;
            } else {
                while (g_flag[g] < target) { }
                __threadfence();
            }
        }
        __syncthreads();
    }
}

extern "C" void kernel_launch(void* const* d_in, const int* in_sizes, int n_in,
                              void* d_out, int out_size) {
    (void)in_sizes; (void)n_in; (void)out_size;
    const float* input  = (const float*)d_in[0];  // (2048, 32, 128)
    const float* h_init = (const float*)d_in[1];  // (32, 1024)
    const float* W_in   = (const float*)d_in[2];  // (1024, 128)
    const float* bias   = (const float*)d_in[3];  // (1024)
    const float* W_h    = (const float*)d_in[4];  // (1024, 1024)
    float* out = (float*)d_out;                   // (2048, 32, 1024)

    cudaFuncSetAttribute(reservoir_persistent,
                         cudaFuncAttributeMaxDynamicSharedMemorySize,
                         SM_TOT * (int)sizeof(float));
    reservoir_persistent<<<GRID, NTHR, SM_TOT * sizeof(float)>>>(
        input, h_init, W_in, bias, W_h, out);
}

// round 6
// speedup vs baseline: 1.3404x; 1.1266x over previous
#include <cuda_runtime.h>
#include <cstdint>

// Problem constants
#define HID   1024
#define INP   128
#define NBAT  32
#define LSTEP 2048
#define KTOT  1152            // 1024 (h) + 128 (x)
#define COLS  64              // hidden columns per CTA (lane covers 2)
#define ROWSB 4               // batch rows per CTA
#define NCOLB 16              // column blocks
#define NBATB 8               // batch groups
#define GRID  (NCOLB * NBATB) // 128 CTAs (single wave)
#define NTHR  512
#define NWARP 16
#define KW    (KTOT / NWARP)  // 72 k per warp
#define NCH   (KW / 4)        // 18 chunks of 4 k
#define NWF   (KW / 2)        // 36 f32x2 W registers (column 0)

// Per-GROUP barrier state (R4/R5's proven protocol, verbatim; 8 groups now).
__device__ unsigned g_cnt[NBATB];
__device__ volatile unsigned g_flag[NBATB];

// Packed dual fp32 FMA (sm_100+)
__device__ __forceinline__ unsigned long long fma2(unsigned long long a,
                                                   unsigned long long b,
                                                   unsigned long long c) {
    unsigned long long d;
    asm("fma.rn.f32x2 %0, %1, %2, %3;" : "=l"(d) : "l"(a), "l"(b), "l"(c));
    return d;
}

__device__ __forceinline__ unsigned long long pack2(float x, float y) {
    unsigned long long r;
    asm("mov.b64 %0, {%1, %2};" : "=l"(r) : "f"(x), "f"(y));
    return r;
}

__device__ __forceinline__ float unpack_sum(unsigned long long v) {
    float lo, hi;
    asm("mov.b64 {%0, %1}, %2;" : "=f"(lo), "=f"(hi) : "l"(v));
    return lo + hi;
}

// smem layout (floats):
//   Ws    [288][32][4]    : 36864   (W for col1 = j0+32+lane; [chunk][lane][4k])
//   HP    [ROWSB][KTOT]   :  4608   ([h(t-1) | x_t] per row)
//   part  [ROWSB][COLS][17]: 4352   (pad 17 -> conflict-free)
//   bias_s[COLS]          :    64
#define HROW   KTOT
#define SM_WS  0
#define SM_HP  (288 * 32 * 4)
#define SM_P   (SM_HP + ROWSB * HROW)
#define PSTR   17
#define SM_B   (SM_P + ROWSB * COLS * PSTR)
#define SM_TOT (SM_B + COLS)            // 45888 floats = 183552 bytes

__global__ void __launch_bounds__(NTHR, 1)
reservoir_persistent(const float* __restrict__ input,   // (L, N, I)
                     const float* __restrict__ h_init,  // (N, H)
                     const float* __restrict__ W_in,    // (H, I)
                     const float* __restrict__ bias,    // (H)
                     const float* __restrict__ W_h,     // (H, H)
                     float* __restrict__ out)           // (L, N, H)
{
    extern __shared__ float smem[];
    float* Ws     = smem + SM_WS;
    float* HP     = smem + SM_HP;
    float* part_s = smem + SM_P;
    float* bias_s = smem + SM_B;

    const int tid = threadIdx.x;
    const int bx  = blockIdx.x;
    const int c   = bx & (NCOLB - 1);   // column block id (0..15)
    const int g   = bx >> 4;            // batch group id (0..7)
    const int j0  = c * COLS;
    const int n0  = g * ROWSB;

    // Epoch base for this group's barrier (tid0 only)
    unsigned bar_base = 0;
    if (tid == 0) bar_base = g_flag[g];

    const int w    = tid >> 5;          // warp id = K-slice (72 k)
    const int lane = tid & 31;
    const int k0   = w * KW;
    const int col0 = j0 + lane;         // W in registers
    // col1 = j0 + 32 + lane            // W in shared

    // ---- One-time: W for col0 into registers (f32x2 packed; boundaries even) ----
    unsigned long long w0[NWF];
    #pragma unroll
    for (int i = 0; i < NWF; ++i) {
        int k = k0 + 2 * i;
        float2 v;
        if (k < HID) v = *(const float2*)(W_h + (size_t)col0 * HID + k);
        else         v = *(const float2*)(W_in + (size_t)col0 * INP + (k - HID));
        w0[i] = pack2(v.x, v.y);
    }
    // ---- One-time: W for col1 into shared: Ws[cg][l][kk], cg=global 4k-chunk ----
    for (int i = tid; i < 288 * 32 * 4; i += NTHR) {
        int kk = i & 3;
        int l  = (i >> 2) & 31;
        int cg = i >> 7;
        int k  = 4 * cg + kk;
        int cl = j0 + 32 + l;
        float v = (k < HID) ? W_h[(size_t)cl * HID + k]
                            : W_in[(size_t)cl * INP + (k - HID)];
        Ws[i] = v;
    }
    if (tid < COLS) bias_s[tid] = bias[j0 + tid];
    __syncthreads();

    // Reduction indices (first 256 threads)
    const int rn = tid >> 6;       // 0..3
    const int rj = tid & 63;       // 0..63

    const char* abase = (const char*)HP + (size_t)k0 * 4;   // warp's k origin
    const ulonglong2* wsp = (const ulonglong2*)Ws + (size_t)(w * NCH) * 32 + lane;

    for (int t = 0; t < LSTEP; ++t) {
        // ---- Stage h(t-1): 4 rows x 1024 floats = 1024 float4 (2 reps) ----
        const float* hsrc = (t == 0) ? (h_init + (size_t)n0 * HID)
                                     : (out + ((size_t)(t - 1) * NBAT + n0) * HID);
        #pragma unroll
        for (int rep = 0; rep < 2; ++rep) {
            int i = tid + rep * NTHR;   // 0..1023
            int n = i >> 8;
            int q = i & 255;
            float4 v = ((const float4*)(hsrc + (size_t)n * HID))[q];
            *(float4*)(HP + n * HROW + 4 * q) = v;
        }
        // ---- Stage x_t: 4 rows x 32 float4 ----
        if (tid < 128) {
            int n = tid >> 5;
            int q = tid & 31;
            float4 v = ((const float4*)(input + ((size_t)t * NBAT + n0 + n) * INP))[q];
            *(float4*)(HP + n * HROW + HID + 4 * q) = v;
        }
        __syncthreads();

        // ---- Compute: lane = 2 cols; h broadcast; W reg (col0) + smem (col1) ----
        unsigned long long acc[2 * ROWSB];   // [2r]=col0, [2r+1]=col1
        #pragma unroll
        for (int i = 0; i < 2 * ROWSB; ++i) acc[i] = 0ull;

        #pragma unroll
        for (int ch = 0; ch < NCH; ++ch) {
            ulonglong2 wv = wsp[ch * 32];    // col1 W, 4k, conflict-free
            #pragma unroll
            for (int r = 0; r < ROWSB; ++r) {
                ulonglong2 a = *(const ulonglong2*)(abase + r * (HROW * 4) + 16 * ch);
                acc[2 * r]     = fma2(a.x, w0[2 * ch],     acc[2 * r]);
                acc[2 * r]     = fma2(a.y, w0[2 * ch + 1], acc[2 * r]);
                acc[2 * r + 1] = fma2(a.x, wv.x,           acc[2 * r + 1]);
                acc[2 * r + 1] = fma2(a.y, wv.y,           acc[2 * r + 1]);
            }
        }

        // ---- Dump partials: part[r][col][w], stride-17 conflict-free ----
        #pragma unroll
        for (int r = 0; r < ROWSB; ++r) {
            part_s[(r * COLS + lane) * PSTR + w]        = unpack_sum(acc[2 * r]);
            part_s[(r * COLS + 32 + lane) * PSTR + w]   = unpack_sum(acc[2 * r + 1]);
        }
        __syncthreads();

        // ---- Reduce 16 partials + bias + tanh + store h(t) ----
        if (tid < 256) {
            float s = bias_s[rj];
            #pragma unroll
            for (int ww = 0; ww < NWARP; ++ww)
                s += part_s[(rn * COLS + rj) * PSTR + ww];
            float hv = tanhf(s);
            out[((size_t)t * NBAT + n0 + rn) * HID + j0 + rj] = hv;
        }
        __syncthreads();

        // ---- Group-wide barrier (proven protocol, 16 CTAs/group) ----
        if (tid == 0) {
            __threadfence();
            unsigned target = bar_base + (unsigned)t + 1u;
            if (atomicAdd(&g_cnt[g], 1u) == (unsigned)(NCOLB - 1)) {
                g_cnt[g] = 0u;
                __threadfence();
                g_flag[g] = target;
            } else {
                while (g_flag[g] < target) { }
                __threadfence();
            }
        }
        __syncthreads();
    }
}

extern "C" void kernel_launch(void* const* d_in, const int* in_sizes, int n_in,
                              void* d_out, int out_size) {
    (void)in_sizes; (void)n_in; (void)out_size;
    const float* input  = (const float*)d_in[0];  // (2048, 32, 128)
    const float* h_init = (const float*)d_in[1];  // (32, 1024)
    const float* W_in   = (const float*)d_in[2];  // (1024, 128)
    const float* bias   = (const float*)d_in[3];  // (1024)
    const float* W_h    = (const float*)d_in[4];  // (1024, 1024)
    float* out = (float*)d_out;                   // (2048, 32, 1024)

    cudaFuncSetAttribute(reservoir_persistent,
                         cudaFuncAttributeMaxDynamicSharedMemorySize,
                         SM_TOT * (int)sizeof(float));
    reservoir_persistent<<<GRID, NTHR, SM_TOT * sizeof(float)>>>(
        input, h_init, W_in, bias, W_h, out);
}